// round 3
// baseline (speedup 1.0000x reference)
#include <cuda_runtime.h>

#define NB   8192
#define ND   1024
#define NE   32
#define NA   128

#define BM   64
#define BN   128
#define BK   64
#define XPAD 66
#define WPAD 130
#define NKT  (ND / BK)
#define NIT  (NKT * NE)

typedef unsigned long long ull;

__device__ float g_weights[NB * NE];

__device__ __forceinline__ ull pack2(float lo, float hi) {
    ull r; asm("mov.b64 %0, {%1, %2};" : "=l"(r) : "f"(lo), "f"(hi)); return r;
}
__device__ __forceinline__ ull fma2(ull a, ull b, ull c) {
    ull d; asm("fma.rn.f32x2 %0, %1, %2, %3;" : "=l"(d) : "l"(a), "l"(b), "l"(c)); return d;
}

// ---------------- gating: logits -> gumbel-softmax weights [B,E] -------------
__global__ void gate_kernel(const float* __restrict__ x,
                            const float* __restrict__ Watt,
                            const float* __restrict__ batt,
                            const float* __restrict__ abias,
                            const float* __restrict__ gum) {
    const int lane = threadIdx.x & 31;
    const int row  = blockIdx.x * (blockDim.x >> 5) + (threadIdx.x >> 5);

    const float4* xr = reinterpret_cast<const float4*>(x + (size_t)row * ND);
    const float4* wr = reinterpret_cast<const float4*>(Watt + (size_t)lane * ND);

    float a0 = 0.f, a1 = 0.f, a2 = 0.f, a3 = 0.f;
#pragma unroll 8
    for (int i = 0; i < ND / 4; ++i) {
        float4 xv = xr[i];
        float4 wv = wr[i];
        a0 = fmaf(xv.x, wv.x, a0);
        a1 = fmaf(xv.y, wv.y, a1);
        a2 = fmaf(xv.z, wv.z, a2);
        a3 = fmaf(xv.w, wv.w, a3);
    }
    float logit = (a0 + a1) + (a2 + a3) + batt[lane] + abias[lane];

    float u = gum[row * NE + lane];
    logit += -logf(-logf(u + 1e-10f) + 1e-10f);   // gumbel noise, TAU = 1

    float mx = logit;
#pragma unroll
    for (int o = 16; o > 0; o >>= 1) mx = fmaxf(mx, __shfl_xor_sync(0xffffffffu, mx, o));
    float p = expf(logit - mx);
    float s = p;
#pragma unroll
    for (int o = 16; o > 0; o >>= 1) s += __shfl_xor_sync(0xffffffffu, s, o);

    g_weights[row * NE + lane] = p / s;
}

// ------------- fused superposition GEMM: out[b,a] = sum_e w*(x@W_e^T + b_e) --
__global__ void __launch_bounds__(256, 1)
strat_kernel(const float* __restrict__ x,
             const float* __restrict__ Wstrat,
             const float* __restrict__ bstrat,
             float* __restrict__ out) {
    extern __shared__ float sm[];
    float* xs  = sm;                                   // 2*BK*XPAD, [k][m]
    float* ws  = sm + 2 * BK * XPAD;                   // 2*BK*WPAD, [k][n]
    float* w_s = sm + 2 * BK * XPAD + 2 * BK * WPAD;   // NE*BM, [e][m]

    const int tid  = threadIdx.x;
    const int b0   = blockIdx.x * BM;
    const int tcol = tid & 15;    // n = 2*tcol + 32*c, c=0..3
    const int trow = tid >> 4;    // m = 2*trow(+1), 2*trow+32(+33)
    const int kk   = tid & 63;
    const int r0   = tid >> 6;

    // gating weights for this CTA's 64 rows -> [e][m]
#pragma unroll
    for (int p = 0; p < 8; ++p) {
        int i = tid + p * 256;                          // i = m*32 + e
        w_s[(i & 31) * BM + (i >> 5)] = g_weights[b0 * NE + i];
    }

    // initial prefetch (kt=0, e=0)
    float wpf[32], xpf[16];
#pragma unroll
    for (int p = 0; p < 32; ++p)
        wpf[p] = Wstrat[(size_t)(r0 + 4 * p) * ND + kk];
#pragma unroll
    for (int p = 0; p < 16; ++p)
        xpf[p] = x[(size_t)(b0 + r0 + 4 * p) * ND + kk];

    ull acc[4][4];
#pragma unroll
    for (int j = 0; j < 4; ++j)
#pragma unroll
        for (int c = 0; c < 4; ++c) acc[j][c] = 0ull;

    for (int it = 0; it < NIT; ++it) {
        const int e   = it & 31;
        const int cur = it & 1;
        const int xb  = (it >> 5) & 1;
        float* wsc = ws + cur * BK * WPAD;
        float* xsc = xs + xb * BK * XPAD;

        // commit prefetched tiles
#pragma unroll
        for (int p = 0; p < 32; ++p) wsc[kk * WPAD + r0 + 4 * p] = wpf[p];
        if (e == 0) {
#pragma unroll
            for (int p = 0; p < 16; ++p) xsc[kk * XPAD + r0 + 4 * p] = xpf[p];
        }
        __syncthreads();

        // prefetch next iteration (hidden behind compute)
        if (it + 1 < NIT) {
            const int nit = it + 1, nkt = nit >> 5, ne = nit & 31;
            const float* wb = Wstrat + (size_t)ne * NA * ND + (size_t)nkt * BK + kk;
#pragma unroll
            for (int p = 0; p < 32; ++p) wpf[p] = wb[(size_t)(r0 + 4 * p) * ND];
            if (ne == 0) {
                const float* xbp = x + (size_t)b0 * ND + (size_t)nkt * BK + kk;
#pragma unroll
                for (int p = 0; p < 16; ++p) xpf[p] = xbp[(size_t)(r0 + 4 * p) * ND];
            }
        }

        // per-expert partial; bias folded in on the first k-tile (it < 32 <=> kt==0)
        ull part[4][4];
        if (it < NE) {
            const float* bb = bstrat + e * NA + 2 * tcol;
#pragma unroll
            for (int c = 0; c < 4; ++c) {
                ull bv = *(const ull*)(bb + 32 * c);
#pragma unroll
                for (int j = 0; j < 4; ++j) part[j][c] = bv;
            }
        } else {
#pragma unroll
            for (int j = 0; j < 4; ++j)
#pragma unroll
                for (int c = 0; c < 4; ++c) part[j][c] = 0ull;
        }

#pragma unroll 16
        for (int k = 0; k < BK; ++k) {
            float2 a01 = *(const float2*)&xsc[k * XPAD + 2 * trow];
            float2 a23 = *(const float2*)&xsc[k * XPAD + 2 * trow + 32];
            ull ad0 = pack2(a01.x, a01.x);
            ull ad1 = pack2(a01.y, a01.y);
            ull ad2 = pack2(a23.x, a23.x);
            ull ad3 = pack2(a23.y, a23.y);
            ull bb0 = *(const ull*)&wsc[k * WPAD + 2 * tcol];
            ull bb1 = *(const ull*)&wsc[k * WPAD + 2 * tcol + 32];
            ull bb2 = *(const ull*)&wsc[k * WPAD + 2 * tcol + 64];
            ull bb3 = *(const ull*)&wsc[k * WPAD + 2 * tcol + 96];
            part[0][0] = fma2(ad0, bb0, part[0][0]);
            part[0][1] = fma2(ad0, bb1, part[0][1]);
            part[0][2] = fma2(ad0, bb2, part[0][2]);
            part[0][3] = fma2(ad0, bb3, part[0][3]);
            part[1][0] = fma2(ad1, bb0, part[1][0]);
            part[1][1] = fma2(ad1, bb1, part[1][1]);
            part[1][2] = fma2(ad1, bb2, part[1][2]);
            part[1][3] = fma2(ad1, bb3, part[1][3]);
            part[2][0] = fma2(ad2, bb0, part[2][0]);
            part[2][1] = fma2(ad2, bb1, part[2][1]);
            part[2][2] = fma2(ad2, bb2, part[2][2]);
            part[2][3] = fma2(ad2, bb3, part[2][3]);
            part[3][0] = fma2(ad3, bb0, part[3][0]);
            part[3][1] = fma2(ad3, bb1, part[3][1]);
            part[3][2] = fma2(ad3, bb2, part[3][2]);
            part[3][3] = fma2(ad3, bb3, part[3][3]);
        }

        // fold with gating weight w[b,e]
        float2 wa  = *(const float2*)&w_s[e * BM + 2 * trow];
        float2 wb2 = *(const float2*)&w_s[e * BM + 2 * trow + 32];
        ull wd0 = pack2(wa.x,  wa.x),  wd1 = pack2(wa.y,  wa.y);
        ull wd2 = pack2(wb2.x, wb2.x), wd3 = pack2(wb2.y, wb2.y);
#pragma unroll
        for (int c = 0; c < 4; ++c) {
            acc[0][c] = fma2(wd0, part[0][c], acc[0][c]);
            acc[1][c] = fma2(wd1, part[1][c], acc[1][c]);
            acc[2][c] = fma2(wd2, part[2][c], acc[2][c]);
            acc[3][c] = fma2(wd3, part[3][c], acc[3][c]);
        }
    }

    // write out: acc[j][c] holds (n, n+1) packed; ull layout == float2 layout
    const int mrow[4] = {2 * trow, 2 * trow + 1, 2 * trow + 32, 2 * trow + 33};
#pragma unroll
    for (int j = 0; j < 4; ++j) {
        float* orow = out + (size_t)(b0 + mrow[j]) * NA + 2 * tcol;
#pragma unroll
        for (int c = 0; c < 4; ++c)
            *(ull*)(orow + 32 * c) = acc[j][c];
    }
}

extern "C" void kernel_launch(void* const* d_in, const int* in_sizes, int n_in,
                              void* d_out, int out_size) {
    const float* x      = (const float*)d_in[0];
    const float* Watt   = (const float*)d_in[1];
    const float* batt   = (const float*)d_in[2];
    const float* abias  = (const float*)d_in[3];
    const float* Wstrat = (const float*)d_in[4];
    const float* bstrat = (const float*)d_in[5];
    const float* gum    = (const float*)d_in[6];
    float* out          = (float*)d_out;

    // gating: 1 warp per row, 8 warps per block
    gate_kernel<<<NB / 8, 256>>>(x, Watt, batt, abias, gum);

    const int smem = (2 * BK * XPAD + 2 * BK * WPAD + NE * BM) * sizeof(float);
    cudaFuncSetAttribute(strat_kernel,
                         cudaFuncAttributeMaxDynamicSharedMemorySize, smem);
    strat_kernel<<<NB / BM, 256, smem>>>(x, Wstrat, bstrat, out);
}

// round 5
// speedup vs baseline: 3.1407x; 3.1407x over previous
#include <cuda_runtime.h>
#include <cstdint>

#define NB   8192
#define ND   1024
#define NE   32
#define NA   128
#define NBNA (NB * NA)

// ---------------- device-global scratch (no allocs) ----------------
__device__ float g_weights[NB * NE];
__device__ float g_part[2 * NBNA];
__device__ float g_xr[NB * ND];           // tf32-rounded x
__device__ float g_wr[NE * NA * ND];      // tf32-rounded W_strat

// ---------------- helpers ----------------
__device__ __forceinline__ uint32_t smem_u32(const void* p) {
    uint32_t a;
    asm("{ .reg .u64 t; cvta.to.shared.u64 t, %1; cvt.u32.u64 %0, t; }" : "=r"(a) : "l"(p));
    return a;
}
__device__ __forceinline__ void cp16(uint32_t dst, const void* src) {
    asm volatile("cp.async.cg.shared.global [%0], [%1], 16;" :: "r"(dst), "l"(src) : "memory");
}
#define CP_COMMIT() asm volatile("cp.async.commit_group;" ::: "memory")
template <int N> __device__ __forceinline__ void cp_wait() {
    asm volatile("cp.async.wait_group %0;" :: "n"(N) : "memory");
}
__device__ __forceinline__ float tf32r(float f) {
    uint32_t r; asm("cvt.rna.tf32.f32 %0, %1;" : "=r"(r) : "f"(f));
    return __uint_as_float(r);
}
__device__ __forceinline__ void mma8(float* d, const uint32_t* a, const uint32_t* b) {
    asm volatile("mma.sync.aligned.m16n8k8.row.col.f32.tf32.tf32.f32 "
                 "{%0,%1,%2,%3}, {%4,%5,%6,%7}, {%8,%9}, {%0,%1,%2,%3};"
                 : "+f"(d[0]), "+f"(d[1]), "+f"(d[2]), "+f"(d[3])
                 : "r"(a[0]), "r"(a[1]), "r"(a[2]), "r"(a[3]),
                   "r"(b[0]), "r"(b[1]));
}

// smem layout for strat kernel (floats, stride 36 per row => 144 B, 16B aligned)
#define TSTR  36
#define TILE_B (128 * TSTR * 4)          // 18432 B per tile
#define XS0   0
#define XS1   TILE_B
#define WS0   (2 * TILE_B)
#define WS1   (3 * TILE_B)
#define WSMO  (4 * TILE_B)               // w_sm: 16*128 floats = 8192 B
#define SMEM_STRAT (WSMO + 8192)

// ============================================================================
// Kernel 0: round to tf32 grid (exact pass-through to mma afterwards)
// ============================================================================
__global__ void __launch_bounds__(256)
round_kernel(const float* __restrict__ src, float* __restrict__ dst, int n4) {
    int i = blockIdx.x * blockDim.x + threadIdx.x;
    if (i < n4) {
        float4 v = ((const float4*)src)[i];
        v.x = tf32r(v.x); v.y = tf32r(v.y); v.z = tf32r(v.z); v.w = tf32r(v.w);
        ((float4*)dst)[i] = v;
    }
}

// ============================================================================
// Kernel 1: gating (full fp32) — 16 rows/block, smem-staged W_att
// ============================================================================
__global__ void __launch_bounds__(256)
gate_kernel(const float* __restrict__ x,  const float* __restrict__ Watt,
            const float* __restrict__ batt, const float* __restrict__ abias,
            const float* __restrict__ gum) {
    __shared__ float Wsm[NE * 64];
    __shared__ float red[8 * 33 * 32];

    const int tid  = threadIdx.x;
    const int lane = tid & 31;
    const int wid  = tid >> 5;
    const int r0   = blockIdx.x * 16 + wid * 2;
    const int r1   = r0 + 1;

    float la[NE], lb[NE];
#pragma unroll
    for (int e = 0; e < NE; ++e) { la[e] = 0.f; lb[e] = 0.f; }

    for (int kt = 0; kt < 16; ++kt) {
        __syncthreads();
#pragma unroll
        for (int p = 0; p < 4; ++p) {
            int idx = tid + 256 * p;
            int e = idx >> 5, k2 = idx & 31;
            *(float2*)&Wsm[e * 64 + k2 * 2] =
                *(const float2*)&Watt[(size_t)e * ND + kt * 64 + k2 * 2];
        }
        __syncthreads();
        float2 xa = *(const float2*)&x[(size_t)r0 * ND + kt * 64 + lane * 2];
        float2 xb = *(const float2*)&x[(size_t)r1 * ND + kt * 64 + lane * 2];
#pragma unroll
        for (int e = 0; e < NE; ++e) {
            float2 wv = *(const float2*)&Wsm[e * 64 + lane * 2];
            la[e] = fmaf(xa.x, wv.x, fmaf(xa.y, wv.y, la[e]));
            lb[e] = fmaf(xb.x, wv.x, fmaf(xb.y, wv.y, lb[e]));
        }
    }

    float* pr = &red[wid * 33 * 32];
#pragma unroll
    for (int half = 0; half < 2; ++half) {
        float* src = half ? lb : la;
        int row = half ? r1 : r0;
#pragma unroll
        for (int e = 0; e < NE; ++e) pr[lane * 33 + e] = src[e];
        __syncwarp();
        float logit = 0.f;
#pragma unroll
        for (int l = 0; l < 32; ++l) logit += pr[l * 33 + lane];
        logit += batt[lane] + abias[lane];
        float u = gum[row * NE + lane];
        logit += -logf(-logf(u + 1e-10f) + 1e-10f);
        float mx = logit;
#pragma unroll
        for (int o = 16; o > 0; o >>= 1) mx = fmaxf(mx, __shfl_xor_sync(0xffffffffu, mx, o));
        float p = expf(logit - mx);
        float s = p;
#pragma unroll
        for (int o = 16; o > 0; o >>= 1) s += __shfl_xor_sync(0xffffffffu, s, o);
        g_weights[row * NE + lane] = p / s;
        __syncwarp();
    }
}

// ============================================================================
// Kernel 2: fused superposition GEMM via legacy tensor-core mma (tf32)
// ============================================================================
__device__ __forceinline__ void load_xw(const float* __restrict__ xr,
                                        const float* __restrict__ wr,
                                        int m0, int eidx, int kt,
                                        uint32_t xs, uint32_t ws, int tid) {
#pragma unroll
    for (int p = 0; p < 4; ++p) {
        int idx = tid + 256 * p;
        int r = idx >> 3, c = idx & 7;
        cp16(xs + r * (TSTR * 4) + c * 16,
             xr + (size_t)(m0 + r) * ND + kt * 32 + c * 4);
    }
#pragma unroll
    for (int p = 0; p < 4; ++p) {
        int idx = tid + 256 * p;
        int r = idx >> 3, c = idx & 7;
        cp16(ws + r * (TSTR * 4) + c * 16,
             wr + (size_t)eidx * NA * ND + (size_t)r * ND + kt * 32 + c * 4);
    }
}

__global__ void __launch_bounds__(256, 1)
strat_mma_kernel(const float* __restrict__ xr, const float* __restrict__ wr) {
    extern __shared__ char dynsm[];
    const uint32_t smb = smem_u32(dynsm);
    const int tid    = threadIdx.x;
    const int lane   = tid & 31;
    const int wid    = tid >> 5;
    const int warp_m = wid & 1;     // 2 x 64-row blocks
    const int warp_n = wid >> 1;    // 4 x 32-col blocks
    const int g      = lane >> 2;
    const int c      = lane & 3;
    const int m0     = blockIdx.x * 128;
    const int z      = blockIdx.y;
    const int ebase  = z * 16;

    // stage gating weights: w_sm[e*128 + m]
    float* w_sm = (float*)(dynsm + WSMO);
#pragma unroll
    for (int p = 0; p < 8; ++p) {
        int idx = tid + 256 * p;          // e = idx>>7, m = idx&127
        w_sm[idx] = g_weights[(size_t)(m0 + (idx & 127)) * NE + ebase + (idx >> 7)];
    }

    float acc[4][4][4];
#pragma unroll
    for (int tm = 0; tm < 4; ++tm)
#pragma unroll
        for (int tn = 0; tn < 4; ++tn)
#pragma unroll
            for (int q = 0; q < 4; ++q) acc[tm][tn][q] = 0.f;

    float part[4][4][4];

    // prologue: iteration 0 tiles -> buffer 0
    load_xw(xr, wr, m0, ebase, 0, smb + XS0, smb + WS0, tid);
    CP_COMMIT();

    for (int it = 0; it < 512; ++it) {
        const int kt = it & 31;
        const int b  = it & 1;

        __syncthreads();   // everyone done reading buf^1 (compute of it-1)
        if (it + 1 < 512) {
            const int ni = it + 1;
            load_xw(xr, wr, m0, ebase + (ni >> 5), ni & 31,
                    smb + (b ? XS0 : XS1), smb + (b ? WS0 : WS1), tid);
            CP_COMMIT();
            cp_wait<1>();
        } else {
            cp_wait<0>();
        }
        __syncthreads();   // tiles for `it` visible to all warps

        const uint32_t* xsu = (const uint32_t*)(dynsm + (b ? XS1 : XS0));
        const uint32_t* wsu = (const uint32_t*)(dynsm + (b ? WS1 : WS0));

        if (kt == 0) {
#pragma unroll
            for (int tm = 0; tm < 4; ++tm)
#pragma unroll
                for (int tn = 0; tn < 4; ++tn)
#pragma unroll
                    for (int q = 0; q < 4; ++q) part[tm][tn][q] = 0.f;
        }

#pragma unroll
        for (int ks = 0; ks < 4; ++ks) {
            const int kc = ks * 8;
            uint32_t a[4][4], bb[4][2];
#pragma unroll
            for (int tm = 0; tm < 4; ++tm) {
                const uint32_t* xrow = xsu + (warp_m * 64 + tm * 16 + g) * TSTR + kc + c;
                a[tm][0] = xrow[0];
                a[tm][2] = xrow[4];
                a[tm][1] = xrow[8 * TSTR];
                a[tm][3] = xrow[8 * TSTR + 4];
            }
#pragma unroll
            for (int tn = 0; tn < 4; ++tn) {
                const uint32_t* wrow = wsu + (warp_n * 32 + tn * 8 + g) * TSTR + kc + c;
                bb[tn][0] = wrow[0];
                bb[tn][1] = wrow[4];
            }
#pragma unroll
            for (int tm = 0; tm < 4; ++tm)
#pragma unroll
                for (int tn = 0; tn < 4; ++tn)
                    mma8(part[tm][tn], a[tm], bb[tn]);
        }

        if (kt == 31) {                   // fold this expert: acc += w * part
            const int e = it >> 5;
#pragma unroll
            for (int tm = 0; tm < 4; ++tm) {
                float wlo = w_sm[e * 128 + warp_m * 64 + tm * 16 + g];
                float whi = w_sm[e * 128 + warp_m * 64 + tm * 16 + g + 8];
#pragma unroll
                for (int tn = 0; tn < 4; ++tn) {
                    acc[tm][tn][0] = fmaf(wlo, part[tm][tn][0], acc[tm][tn][0]);
                    acc[tm][tn][1] = fmaf(wlo, part[tm][tn][1], acc[tm][tn][1]);
                    acc[tm][tn][2] = fmaf(whi, part[tm][tn][2], acc[tm][tn][2]);
                    acc[tm][tn][3] = fmaf(whi, part[tm][tn][3], acc[tm][tn][3]);
                }
            }
        }
    }

    // epilogue: write half-partial to g_part[z]
    float* dst = g_part + (size_t)z * NBNA;
#pragma unroll
    for (int tm = 0; tm < 4; ++tm) {
        const int row = m0 + warp_m * 64 + tm * 16 + g;
#pragma unroll
        for (int tn = 0; tn < 4; ++tn) {
            const int col = warp_n * 32 + tn * 8 + 2 * c;
            *(float2*)&dst[(size_t)row * NA + col] =
                make_float2(acc[tm][tn][0], acc[tm][tn][1]);
            *(float2*)&dst[(size_t)(row + 8) * NA + col] =
                make_float2(acc[tm][tn][2], acc[tm][tn][3]);
        }
    }
}

// ============================================================================
// Kernel 3: sum halves + weighted bias
// ============================================================================
__global__ void __launch_bounds__(256)
reduce_kernel(const float* __restrict__ bstrat, float* __restrict__ out) {
    __shared__ float bs[NE * NA];
    __shared__ float wsh[8 * NE];
    const int tid = threadIdx.x;
    const int b0  = blockIdx.x * 8;
#pragma unroll
    for (int p = 0; p < 16; ++p) bs[tid + 256 * p] = bstrat[tid + 256 * p];
    wsh[tid] = g_weights[(size_t)b0 * NE + tid];
    __syncthreads();

    const int row = tid >> 5;
    const int n4  = (tid & 31) * 4;
    const size_t b = b0 + row;
    float4 a  = *(const float4*)&g_part[b * NA + n4];
    float4 p1 = *(const float4*)&g_part[NBNA + b * NA + n4];
    a.x += p1.x; a.y += p1.y; a.z += p1.z; a.w += p1.w;
#pragma unroll
    for (int e = 0; e < NE; ++e) {
        float w = wsh[row * NE + e];
        float4 bv = *(const float4*)&bs[e * NA + n4];
        a.x = fmaf(w, bv.x, a.x);
        a.y = fmaf(w, bv.y, a.y);
        a.z = fmaf(w, bv.z, a.z);
        a.w = fmaf(w, bv.w, a.w);
    }
    *(float4*)&out[b * NA + n4] = a;
}

// ============================================================================
extern "C" void kernel_launch(void* const* d_in, const int* in_sizes, int n_in,
                              void* d_out, int out_size) {
    const float* x      = (const float*)d_in[0];
    const float* Watt   = (const float*)d_in[1];
    const float* batt   = (const float*)d_in[2];
    const float* abias  = (const float*)d_in[3];
    const float* Wstrat = (const float*)d_in[4];
    const float* bstrat = (const float*)d_in[5];
    const float* gum    = (const float*)d_in[6];
    float* out          = (float*)d_out;

    gate_kernel<<<NB / 16, 256>>>(x, Watt, batt, abias, gum);

    float* xr = nullptr; float* wrp = nullptr;
    cudaGetSymbolAddress((void**)&xr,  g_xr);
    cudaGetSymbolAddress((void**)&wrp, g_wr);
    round_kernel<<<(NB * ND / 4 + 255) / 256, 256>>>(x, xr, NB * ND / 4);
    round_kernel<<<(NE * NA * ND / 4 + 255) / 256, 256>>>(Wstrat, wrp, NE * NA * ND / 4);

    cudaFuncSetAttribute(strat_mma_kernel,
                         cudaFuncAttributeMaxDynamicSharedMemorySize, SMEM_STRAT);
    strat_mma_kernel<<<dim3(NB / 128, 2), 256, SMEM_STRAT>>>(xr, wrp);

    reduce_kernel<<<NB / 8, 256>>>(bstrat, out);
}